// round 8
// baseline (speedup 1.0000x reference)
#include <cuda_runtime.h>
#include <cuda_bf16.h>

#define BINS        10
#define THREADS     128
#define CTAS_PER_SM 8
#define GRID        (148 * CTAS_PER_SM)   // 1184

// Global scratch (allocation-free). Invariant: zero at every kernel entry —
// zero-initialized at load, last CTA of each run resets after writing out.
__device__ float        g_binS[BINS];
__device__ float        g_binC[BINS];
__device__ unsigned int g_ticket;

// Bin index matches reference bit-for-bit: g = |p-t| in fp32,
// idx = trunc(g*10) clipped to 9 (g >= 0 so trunc == floor).
// bce = -(t*log(p) + (1-t)*log(1-p)) = -log(1 - |p-t|) for t in {0,1}.
// Per-thread-private slot hist[idx*THREADS + tid]: 32 lanes of a warp hit 32
// consecutive 8B slots -> conflict-free regardless of idx.
__device__ __forceinline__ void ghm_accum(float p, float t, float2* hist_tid) {
    float g   = fabsf(p - t);
    int   idx = min((int)(g * 10.0f), BINS - 1);
    float bce = -__logf(1.0f - g);
    float2* slot = hist_tid + idx * THREADS;
    float2  a = *slot;
    a.x += bce;
    a.y += 1.0f;
    *slot = a;
}

__device__ __forceinline__ void ghm_accum4(float4 p, float4 t, float2* h) {
    ghm_accum(p.x, t.x, h);
    ghm_accum(p.y, t.y, h);
    ghm_accum(p.z, t.z, h);
    ghm_accum(p.w, t.w, h);
}

__global__ void __launch_bounds__(THREADS, CTAS_PER_SM)
ghm_fused_kernel(const float* __restrict__ inp,
                 const float* __restrict__ tgt,
                 int n4, int n,
                 float* __restrict__ out) {
    // Two independent per-thread-private histogram copies (10 KB each):
    // batch0 -> hist0, batch1 -> hist1, so the two RMW chains overlap.
    __shared__ float2 hist0[BINS * THREADS];
    __shared__ float2 hist1[BINS * THREADS];
    __shared__ bool   s_is_last;
    const int tid = threadIdx.x;

    #pragma unroll
    for (int b = 0; b < BINS; b++) {
        hist0[b * THREADS + tid] = make_float2(0.0f, 0.0f);
        hist1[b * THREADS + tid] = make_float2(0.0f, 0.0f);
    }
    __syncthreads();

    float2* h0 = &hist0[tid];
    float2* h1 = &hist1[tid];

    const float4* __restrict__ P4 = (const float4*)inp;
    const float4* __restrict__ T4 = (const float4*)tgt;
    const int stride = GRID * THREADS;

    int i = blockIdx.x * THREADS + tid;

    // Software-pipelined main loop: prefetch next 2 float4-pairs (4 LDG.128)
    // before processing the current 8 elements -> loads continuously in
    // flight per warp while the smem RMW chains drain.
    if (i + stride < n4) {
        float4 p0 = P4[i];
        float4 t0 = T4[i];
        float4 p1 = P4[i + stride];
        float4 t1 = T4[i + stride];
        i += 2 * stride;
        for (; i + stride < n4; i += 2 * stride) {
            float4 q0 = P4[i];
            float4 u0 = T4[i];
            float4 q1 = P4[i + stride];
            float4 u1 = T4[i + stride];
            ghm_accum4(p0, t0, h0);
            ghm_accum4(p1, t1, h1);
            p0 = q0; t0 = u0; p1 = q1; t1 = u1;
        }
        ghm_accum4(p0, t0, h0);
        ghm_accum4(p1, t1, h1);
    }
    // Remainder float4 pairs (0..2 per thread).
    for (; i < n4; i += stride) {
        float4 p = P4[i];
        float4 t = T4[i];
        ghm_accum4(p, t, h0);
    }
    // Scalar tail (n not divisible by 4).
    for (int j = n4 * 4 + blockIdx.x * THREADS + tid; j < n; j += stride)
        ghm_accum(inp[j], tgt[j], h0);

    __syncthreads();

    // Fold copy 1 into copy 0, then CTA tree reduction over threads.
    #pragma unroll
    for (int b = 0; b < BINS; b++) {
        float2 a = hist0[b * THREADS + tid];
        float2 c = hist1[b * THREADS + tid];
        hist0[b * THREADS + tid] = make_float2(a.x + c.x, a.y + c.y);
    }
    __syncthreads();

    for (int s = THREADS / 2; s > 0; s >>= 1) {
        if (tid < s) {
            #pragma unroll
            for (int b = 0; b < BINS; b++) {
                float2 a = hist0[b * THREADS + tid];
                float2 c = hist0[b * THREADS + tid + s];
                hist0[b * THREADS + tid] = make_float2(a.x + c.x, a.y + c.y);
            }
        }
        __syncthreads();
    }

    // Per-CTA partials into global bins.
    if (tid < BINS) {
        atomicAdd(&g_binS[tid], hist0[tid * THREADS].x);
        atomicAdd(&g_binC[tid], hist0[tid * THREADS].y);
    }
    __threadfence();
    __syncthreads();

    // Last CTA finalizes and resets state for the next graph replay.
    if (tid == 0)
        s_is_last = (atomicAdd(&g_ticket, 1u) == GRID - 1);
    __syncthreads();

    if (s_is_last && tid == 0) {
        __threadfence();
        float nb = 0.0f, accv = 0.0f;
        #pragma unroll
        for (int b = 0; b < BINS; b++) {
            float c = __ldcg(&g_binC[b]);
            float s = __ldcg(&g_binS[b]);
            if (c > 0.0f) {
                nb   += 1.0f;
                accv += s / c;
            }
        }
        out[0] = accv / fmaxf(nb, 1.0f);
        #pragma unroll
        for (int b = 0; b < BINS; b++) { g_binS[b] = 0.0f; g_binC[b] = 0.0f; }
        g_ticket = 0u;
    }
}

extern "C" void kernel_launch(void* const* d_in, const int* in_sizes, int n_in,
                              void* d_out, int out_size) {
    const float* inp = (const float*)d_in[0];
    const float* tgt = (const float*)d_in[1];
    float* out = (float*)d_out;
    int n  = in_sizes[0];
    int n4 = n >> 2;

    ghm_fused_kernel<<<GRID, THREADS>>>(inp, tgt, n4, n, out);
}

// round 9
// speedup vs baseline: 1.2081x; 1.2081x over previous
#include <cuda_runtime.h>
#include <cuda_bf16.h>

#define BINS        10
#define THREADS     256
#define CTAS_PER_SM 5                 // 51-reg budget: room for the pipeline
#define GRID        (148 * CTAS_PER_SM)   // 740

// Global scratch (allocation-free). Invariant: zero at every kernel entry —
// zero-initialized at load, last CTA of each run resets after writing out.
__device__ float        g_binS[BINS];
__device__ float        g_binC[BINS];
__device__ unsigned int g_ticket;

// Bin index matches reference bit-for-bit: g = |p-t| in fp32,
// idx = trunc(g*10) clipped to 9 (g >= 0 so trunc == floor).
// bce = -(t*log(p) + (1-t)*log(1-p)) = -log(1 - |p-t|) for t in {0,1}.
// Per-thread-private slot hist[idx*THREADS + tid]: 32 lanes of a warp hit 32
// consecutive 8B slots -> conflict-free regardless of idx.
__device__ __forceinline__ void ghm_accum(float p, float t, float2* hist_tid) {
    float g   = fabsf(p - t);
    int   idx = min((int)(g * 10.0f), BINS - 1);
    float bce = -__logf(1.0f - g);
    float2* slot = hist_tid + idx * THREADS;
    float2  a = *slot;
    a.x += bce;
    a.y += 1.0f;
    *slot = a;
}

__device__ __forceinline__ void ghm_accum4(float4 p, float4 t, float2* h) {
    ghm_accum(p.x, t.x, h);
    ghm_accum(p.y, t.y, h);
    ghm_accum(p.z, t.z, h);
    ghm_accum(p.w, t.w, h);
}

__global__ void __launch_bounds__(THREADS, CTAS_PER_SM)
ghm_fused_kernel(const float* __restrict__ inp,
                 const float* __restrict__ tgt,
                 int n4, int n,
                 float* __restrict__ out) {
    __shared__ float2 hist[BINS * THREADS];   // 20 KB: [bin][tid]
    __shared__ bool   s_is_last;
    const int tid = threadIdx.x;

    #pragma unroll
    for (int b = 0; b < BINS; b++)
        hist[b * THREADS + tid] = make_float2(0.0f, 0.0f);
    __syncthreads();

    float2* hist_tid = &hist[tid];

    const float4* __restrict__ P4 = (const float4*)inp;
    const float4* __restrict__ T4 = (const float4*)tgt;
    const int stride = GRID * THREADS;

    int i = blockIdx.x * THREADS + tid;

    // Software-pipelined loop: batch k+1's 4 LDG.128 are issued BEFORE
    // batch k's 8 smem-RMWs, so every warp keeps ~2 KB of reads in flight
    // through the chain phase (duty cycle ~1 instead of ~0.5).
    if (i + stride < n4) {
        float4 p0 = P4[i];
        float4 t0 = T4[i];
        float4 p1 = P4[i + stride];
        float4 t1 = T4[i + stride];
        i += 2 * stride;
        for (; i + stride < n4; i += 2 * stride) {
            float4 q0 = P4[i];
            float4 u0 = T4[i];
            float4 q1 = P4[i + stride];
            float4 u1 = T4[i + stride];
            ghm_accum4(p0, t0, hist_tid);
            ghm_accum4(p1, t1, hist_tid);
            p0 = q0; t0 = u0; p1 = q1; t1 = u1;
        }
        ghm_accum4(p0, t0, hist_tid);
        ghm_accum4(p1, t1, hist_tid);
    }
    // Remainder float4 pairs (0..2 per thread).
    for (; i < n4; i += stride) {
        float4 p = P4[i];
        float4 t = T4[i];
        ghm_accum4(p, t, hist_tid);
    }
    // Scalar tail (n not divisible by 4).
    for (int j = n4 * 4 + blockIdx.x * THREADS + tid; j < n; j += stride)
        ghm_accum(inp[j], tgt[j], hist_tid);

    __syncthreads();

    // CTA tree reduction over the thread dimension, all bins per level.
    for (int s = THREADS / 2; s > 0; s >>= 1) {
        if (tid < s) {
            #pragma unroll
            for (int b = 0; b < BINS; b++) {
                float2 a = hist[b * THREADS + tid];
                float2 c = hist[b * THREADS + tid + s];
                hist[b * THREADS + tid] = make_float2(a.x + c.x, a.y + c.y);
            }
        }
        __syncthreads();
    }

    // Per-CTA partials into global bins.
    if (tid < BINS) {
        atomicAdd(&g_binS[tid], hist[tid * THREADS].x);
        atomicAdd(&g_binC[tid], hist[tid * THREADS].y);
    }
    __threadfence();
    __syncthreads();

    // Last CTA finalizes and resets state for the next graph replay.
    if (tid == 0)
        s_is_last = (atomicAdd(&g_ticket, 1u) == GRID - 1);
    __syncthreads();

    if (s_is_last && tid == 0) {
        __threadfence();
        float nb = 0.0f, accv = 0.0f;
        #pragma unroll
        for (int b = 0; b < BINS; b++) {
            float c = __ldcg(&g_binC[b]);
            float s = __ldcg(&g_binS[b]);
            if (c > 0.0f) {
                nb   += 1.0f;
                accv += s / c;
            }
        }
        out[0] = accv / fmaxf(nb, 1.0f);
        #pragma unroll
        for (int b = 0; b < BINS; b++) { g_binS[b] = 0.0f; g_binC[b] = 0.0f; }
        g_ticket = 0u;
    }
}

extern "C" void kernel_launch(void* const* d_in, const int* in_sizes, int n_in,
                              void* d_out, int out_size) {
    const float* inp = (const float*)d_in[0];
    const float* tgt = (const float*)d_in[1];
    float* out = (float*)d_out;
    int n  = in_sizes[0];
    int n4 = n >> 2;

    ghm_fused_kernel<<<GRID, THREADS>>>(inp, tgt, n4, n, out);
}